// round 1
// baseline (speedup 1.0000x reference)
#include <cuda_runtime.h>
#include <math.h>

#define NN       1024
#define NEVALC   131072
#define NPOLES   8
#define NGROUPS  256          // 4 nodes per group
#define PI_D     3.14159265358979323846

typedef unsigned long long ull;

// ---------------- scratch (no allocations allowed) ----------------
__device__ float      g_nodes[NN];
__device__ float      g_logw[NN];
__device__ float      g_w[NN];
__device__ ulonglong2 g_coef[NGROUPS * 7];   // 14 packed-duplicated f32x2 coeffs per group

// ---------------- packed f32x2 helpers (sm_103a) ----------------
__device__ __forceinline__ ull f2fma(ull a, ull b, ull c) {
    ull d; asm("fma.rn.f32x2 %0,%1,%2,%3;" : "=l"(d) : "l"(a), "l"(b), "l"(c)); return d;
}
__device__ __forceinline__ ull f2add(ull a, ull b) {
    ull d; asm("add.rn.f32x2 %0,%1,%2;" : "=l"(d) : "l"(a), "l"(b)); return d;
}
__device__ __forceinline__ ull pk2(float lo, float hi) {
    ull r; asm("mov.b64 %0,{%1,%2};" : "=l"(r) : "f"(lo), "f"(hi)); return r;
}
__device__ __forceinline__ void upk2(ull v, float& lo, float& hi) {
    asm("mov.b64 {%0,%1},%2;" : "=f"(lo), "=f"(hi) : "l"(v));
}
__device__ __forceinline__ float frcp(float a) {
    float r; asm("rcp.approx.f32 %0,%1;" : "=f"(r) : "f"(a)); return r;
}

// ---------------- P0: Chebyshev nodes (double -> f32, matches jnp.cos(pi*linspace)) ----
__global__ void k_nodes() {
    int j = blockIdx.x * blockDim.x + threadIdx.x;
    if (j < NN) {
        double t = (double)j / 1023.0;
        g_nodes[j] = (float)cos(PI_D * t);
    }
}

// ---------------- P1: log-weights (f32, like reference; one warp per node) ----------
__global__ void k_logw(const float* __restrict__ pr, const float* __restrict__ pim) {
    int w  = threadIdx.x >> 5;
    int ln = threadIdx.x & 31;
    int j  = blockIdx.x * 32 + w;
    float nj = g_nodes[j];
    float s = 0.f;
    #pragma unroll 8
    for (int i = ln; i < NN; i += 32)
        if (i != j) s += logf(fabsf(nj - g_nodes[i]));
    #pragma unroll
    for (int off = 16; off; off >>= 1) s += __shfl_xor_sync(0xffffffffu, s, off);
    if (ln == 0) {
        float ps = 0.f;
        #pragma unroll
        for (int p = 0; p < NPOLES; p++) {
            float dr = nj - pr[p];
            ps += logf(dr * dr + pim[p] * pim[p]);
        }
        g_logw[j] = ps - s;   // -sum(log|diff|) + pole terms
    }
}

// ---------------- P2: max-normalize + exp + sign (global scale cancels in num/den) ----
__global__ void k_weights() {
    __shared__ float smax[32];
    int t = threadIdx.x;
    float v = g_logw[t];
    float m = v;
    #pragma unroll
    for (int off = 16; off; off >>= 1) m = fmaxf(m, __shfl_xor_sync(0xffffffffu, m, off));
    if ((t & 31) == 0) smax[t >> 5] = m;
    __syncthreads();
    if (t < 32) {
        float mm = smax[t];
        #pragma unroll
        for (int off = 16; off; off >>= 1) mm = fmaxf(mm, __shfl_xor_sync(0xffffffffu, mm, off));
        if (t == 0) smax[0] = mm;
    }
    __syncthreads();
    float w = expf(v - smax[0]);
    g_w[t] = (t & 1) ? -w : w;         // sign = (-1)^j (nodes strictly descending)
}

// ---------------- P3: per-group rational coefficients (fp64 build -> f32 packed) ------
// Group g: nodes 4g..4g+3. Local var t = x - c (exact in f32 near group).
//   Q(t)  = prod (t - d_i)                     (monic quartic)
//   Pv(t) = sum v_i*w_i * prod_{j!=i}(t - d_j) (cubic)
//   Pw(t) = sum     w_i * prod_{j!=i}(t - d_j) (cubic)
__global__ void k_coef(const float* __restrict__ vals) {
    int g = blockIdx.x * blockDim.x + threadIdx.x;
    if (g >= NGROUPS) return;
    double n[4], d[4], u[4], uv[4];
    #pragma unroll
    for (int i = 0; i < 4; i++) n[i] = (double)g_nodes[4 * g + i];
    float cf = (float)(0.25 * (n[0] + n[1] + n[2] + n[3]));
    #pragma unroll
    for (int i = 0; i < 4; i++) {
        d[i]  = n[i] - (double)cf;
        u[i]  = (double)g_w[4 * g + i];
        uv[i] = u[i] * (double)vals[4 * g + i];
    }
    double e1 = d[0] + d[1] + d[2] + d[3];
    double e2 = d[0]*d[1] + d[0]*d[2] + d[0]*d[3] + d[1]*d[2] + d[1]*d[3] + d[2]*d[3];
    double e3 = d[0]*d[1]*d[2] + d[0]*d[1]*d[3] + d[0]*d[2]*d[3] + d[1]*d[2]*d[3];
    double e4 = d[0]*d[1]*d[2]*d[3];
    double pv3 = 0, pv2 = 0, pv1 = 0, pv0 = 0;
    double pw3 = 0, pw2 = 0, pw1 = 0, pw0 = 0;
    #pragma unroll
    for (int i = 0; i < 4; i++) {
        double s1 = e1 - d[i];            // elementary syms of the 3 other roots
        double s2 = e2 - d[i] * s1;
        double s3 = e3 - d[i] * s2;
        pv3 += uv[i];  pv2 -= uv[i] * s1;  pv1 += uv[i] * s2;  pv0 -= uv[i] * s3;
        pw3 += u[i];   pw2 -= u[i]  * s1;  pw1 += u[i]  * s2;  pw0 -= u[i]  * s3;
    }
    ull* cc = (ull*)g_coef + (size_t)g * 14;
    float f;
    f = -cf;          cc[0]  = pk2(f, f);
    f = (float)(-e1); cc[1]  = pk2(f, f);   // q3
    f = (float)( e2); cc[2]  = pk2(f, f);   // q2
    f = (float)(-e3); cc[3]  = pk2(f, f);   // q1
    f = (float)( e4); cc[4]  = pk2(f, f);   // q0
    f = (float)pv3;   cc[5]  = pk2(f, f);
    f = (float)pv2;   cc[6]  = pk2(f, f);
    f = (float)pv1;   cc[7]  = pk2(f, f);
    f = (float)pv0;   cc[8]  = pk2(f, f);
    f = (float)pw3;   cc[9]  = pk2(f, f);
    f = (float)pw2;   cc[10] = pk2(f, f);
    f = (float)pw1;   cc[11] = pk2(f, f);
    f = (float)pw0;   cc[12] = pk2(f, f);
    cc[13] = 0ull;                          // pad to 7 x 16B
}

// ---------------- main eval: 2 points per thread packed into f32x2 lanes --------------
__global__ __launch_bounds__(128) void k_eval(const float* __restrict__ x,
                                              float* __restrict__ out) {
    __shared__ ulonglong2 sc[NGROUPS * 7];   // 28 KB, broadcast reads
    {
        const uint4* src = (const uint4*)g_coef;
        uint4* dst = (uint4*)sc;
        for (int i = threadIdx.x; i < NGROUPS * 7; i += 128) dst[i] = src[i];
    }
    __syncthreads();

    int pair = blockIdx.x * 128 + threadIdx.x;
    if (pair >= NEVALC / 2) return;
    float2 xv = ((const float2*)x)[pair];
    ull x2  = pk2(xv.x, xv.y);
    ull num = 0ull, den = 0ull;              // two packed 0.0f
    const ulonglong2* cp = sc;

    #pragma unroll 4
    for (int g = 0; g < NGROUPS; g++) {
        ulonglong2 c0 = cp[0], c1 = cp[1], c2 = cp[2], c3 = cp[3],
                   c4 = cp[4], c5 = cp[5], c6 = cp[6];
        cp += 7;
        ull t = f2add(x2, c0.x);                          // t = x - c (exact near group)
        ull q = f2add(t, c0.y);                           // monic quartic Horner
        q  = f2fma(q, t, c1.x);
        q  = f2fma(q, t, c1.y);
        q  = f2fma(q, t, c2.x);
        ull pv = f2fma(c2.y, t, c3.x);                    // cubic Horner
        pv = f2fma(pv, t, c3.y);
        pv = f2fma(pv, t, c4.x);
        ull pw = f2fma(c4.y, t, c5.x);
        pw = f2fma(pw, t, c5.y);
        pw = f2fma(pw, t, c6.x);
        float ql, qh; upk2(q, ql, qh);
        ull r = pk2(frcp(ql), frcp(qh));                  // 1 MUFU per 4 nodes per point
        num = f2fma(pv, r, num);
        den = f2fma(pw, r, den);
    }
    float nl, nh, dl, dh;
    upk2(num, nl, nh);
    upk2(den, dl, dh);
    float2 o;
    o.x = nl * frcp(dl);
    o.y = nh * frcp(dh);
    ((float2*)out)[pair] = o;
}

// ---------------- launch ----------------
extern "C" void kernel_launch(void* const* d_in, const int* in_sizes, int n_in,
                              void* d_out, int out_size) {
    const float* x    = (const float*)d_in[0];
    const float* vals = (const float*)d_in[1];
    const float* pr   = (const float*)d_in[2];
    const float* pim  = (const float*)d_in[3];
    float* out = (float*)d_out;

    k_nodes  <<<4, 256>>>();
    k_logw   <<<32, 1024>>>(pr, pim);
    k_weights<<<1, 1024>>>();
    k_coef   <<<32, 8>>>(vals);
    k_eval   <<<NEVALC / 2 / 128, 128>>>(x, out);
}

// round 2
// speedup vs baseline: 1.2031x; 1.2031x over previous
#include <cuda_runtime.h>
#include <math.h>

#define NN       1024
#define NEVALC   131072
#define NPOLES   8
#define NGROUPS  256          // 4 nodes per group
#define PI_D     3.14159265358979323846
#define LOGC     700.0f       // fixed log-shift (cancels in num/den); keeps expf in range

typedef unsigned long long ull;

// ---------------- scratch (no allocations allowed) ----------------
__device__ float      g_nodes[NN];
__device__ float      g_w[NN];
__device__ ulonglong2 g_coef[NGROUPS * 7];   // 14 packed-duplicated f32x2 coeffs per group

// ---------------- packed f32x2 helpers (sm_103a) ----------------
__device__ __forceinline__ ull f2fma(ull a, ull b, ull c) {
    ull d; asm("fma.rn.f32x2 %0,%1,%2,%3;" : "=l"(d) : "l"(a), "l"(b), "l"(c)); return d;
}
__device__ __forceinline__ ull f2add(ull a, ull b) {
    ull d; asm("add.rn.f32x2 %0,%1,%2;" : "=l"(d) : "l"(a), "l"(b)); return d;
}
__device__ __forceinline__ ull pk2(float lo, float hi) {
    ull r; asm("mov.b64 %0,{%1,%2};" : "=l"(r) : "f"(lo), "f"(hi)); return r;
}
__device__ __forceinline__ void upk2(ull v, float& lo, float& hi) {
    asm("mov.b64 {%0,%1},%2;" : "=f"(lo), "=f"(hi) : "l"(v));
}
__device__ __forceinline__ float frcp(float a) {
    float r; asm("rcp.approx.f32 %0,%1;" : "=f"(r) : "f"(a)); return r;
}

// ---------------- P0: Chebyshev nodes (double -> f32, matches jnp.cos(pi*linspace)) ----
__global__ void k_nodes() {
    int j = blockIdx.x * blockDim.x + threadIdx.x;
    if (j < NN) {
        double t = (double)j / 1023.0;
        g_nodes[j] = (float)cos(PI_D * t);
    }
}

// ---------------- P1: weights (f32 log-sum like reference; one warp per node) --------
// Max-normalization in the reference is a COMMON factor across j and cancels in
// num/den; we subtract the fixed constant LOGC instead (residual stays in f32
// exp range), so no global reduction is needed.
__global__ void k_wts(const float* __restrict__ pr, const float* __restrict__ pim) {
    int w  = threadIdx.x >> 5;
    int ln = threadIdx.x & 31;
    int j  = blockIdx.x * (blockDim.x >> 5) + w;
    float nj = g_nodes[j];
    float s = 0.f;
    #pragma unroll 8
    for (int i = ln; i < NN; i += 32)
        if (i != j) s += logf(fabsf(nj - g_nodes[i]));
    #pragma unroll
    for (int off = 16; off; off >>= 1) s += __shfl_xor_sync(0xffffffffu, s, off);
    if (ln == 0) {
        float ps = 0.f;
        #pragma unroll
        for (int p = 0; p < NPOLES; p++) {
            float dr = nj - pr[p];
            ps += logf(dr * dr + pim[p] * pim[p]);
        }
        float wv = expf(ps - s - LOGC);
        g_w[j] = (j & 1) ? -wv : wv;   // sign = (-1)^j (nodes strictly descending)
    }
}

// ---------------- P2: per-group rational coefficients (fp64 build -> f32 packed) ------
// Group g: nodes 4g..4g+3. Local var t = x - c (exact in f32 near group).
//   Q(t)  = prod (t - d_i)                     (monic quartic)
//   Pv(t) = sum v_i*w_i * prod_{j!=i}(t - d_j) (cubic)
//   Pw(t) = sum     w_i * prod_{j!=i}(t - d_j) (cubic)
__global__ void k_coef(const float* __restrict__ vals) {
    int g = blockIdx.x * blockDim.x + threadIdx.x;
    if (g >= NGROUPS) return;
    double n[4], d[4], u[4], uv[4];
    #pragma unroll
    for (int i = 0; i < 4; i++) n[i] = (double)g_nodes[4 * g + i];
    float cf = (float)(0.25 * (n[0] + n[1] + n[2] + n[3]));
    #pragma unroll
    for (int i = 0; i < 4; i++) {
        d[i]  = n[i] - (double)cf;
        u[i]  = (double)g_w[4 * g + i];
        uv[i] = u[i] * (double)vals[4 * g + i];
    }
    double e1 = d[0] + d[1] + d[2] + d[3];
    double e2 = d[0]*d[1] + d[0]*d[2] + d[0]*d[3] + d[1]*d[2] + d[1]*d[3] + d[2]*d[3];
    double e3 = d[0]*d[1]*d[2] + d[0]*d[1]*d[3] + d[0]*d[2]*d[3] + d[1]*d[2]*d[3];
    double e4 = d[0]*d[1]*d[2]*d[3];
    double pv3 = 0, pv2 = 0, pv1 = 0, pv0 = 0;
    double pw3 = 0, pw2 = 0, pw1 = 0, pw0 = 0;
    #pragma unroll
    for (int i = 0; i < 4; i++) {
        double s1 = e1 - d[i];            // elementary syms of the 3 other roots
        double s2 = e2 - d[i] * s1;
        double s3 = e3 - d[i] * s2;
        pv3 += uv[i];  pv2 -= uv[i] * s1;  pv1 += uv[i] * s2;  pv0 -= uv[i] * s3;
        pw3 += u[i];   pw2 -= u[i]  * s1;  pw1 += u[i]  * s2;  pw0 -= u[i]  * s3;
    }
    ull* cc = (ull*)g_coef + (size_t)g * 14;
    float f;
    f = -cf;          cc[0]  = pk2(f, f);
    f = (float)(-e1); cc[1]  = pk2(f, f);   // q3
    f = (float)( e2); cc[2]  = pk2(f, f);   // q2
    f = (float)(-e3); cc[3]  = pk2(f, f);   // q1
    f = (float)( e4); cc[4]  = pk2(f, f);   // q0
    f = (float)pv3;   cc[5]  = pk2(f, f);
    f = (float)pv2;   cc[6]  = pk2(f, f);
    f = (float)pv1;   cc[7]  = pk2(f, f);
    f = (float)pv0;   cc[8]  = pk2(f, f);
    f = (float)pw3;   cc[9]  = pk2(f, f);
    f = (float)pw2;   cc[10] = pk2(f, f);
    f = (float)pw1;   cc[11] = pk2(f, f);
    f = (float)pw0;   cc[12] = pk2(f, f);
    cc[13] = 0ull;                          // pad to 7 x 16B
}

// ---------------- main eval: 4 points (2 packed f32x2 pairs) per thread --------------
__global__ __launch_bounds__(128) void k_eval(const float* __restrict__ x,
                                              float* __restrict__ out) {
    __shared__ ulonglong2 sc[NGROUPS * 7];   // 28 KB, broadcast reads
    {
        const uint4* src = (const uint4*)g_coef;
        uint4* dst = (uint4*)sc;
        #pragma unroll
        for (int i = threadIdx.x; i < NGROUPS * 7; i += 128) dst[i] = src[i];
    }
    __syncthreads();

    int quad = blockIdx.x * 128 + threadIdx.x;          // 4 consecutive points
    float4 xv = ((const float4*)x)[quad];
    ull xa = pk2(xv.x, xv.y);
    ull xb = pk2(xv.z, xv.w);
    ull numa = 0ull, dena = 0ull, numb = 0ull, denb = 0ull;
    const ulonglong2* cp = sc;

    #pragma unroll 2
    for (int g = 0; g < NGROUPS; g++) {
        ulonglong2 c0 = cp[0], c1 = cp[1], c2 = cp[2], c3 = cp[3],
                   c4 = cp[4], c5 = cp[5], c6 = cp[6];
        cp += 7;
        ull ta = f2add(xa, c0.x);                       // t = x - c (exact near group)
        ull tb = f2add(xb, c0.x);
        ull qa = f2add(ta, c0.y);                       // monic quartic Horner
        ull qb = f2add(tb, c0.y);
        qa = f2fma(qa, ta, c1.x);   qb = f2fma(qb, tb, c1.x);
        qa = f2fma(qa, ta, c1.y);   qb = f2fma(qb, tb, c1.y);
        qa = f2fma(qa, ta, c2.x);   qb = f2fma(qb, tb, c2.x);
        ull pva = f2fma(c2.y, ta, c3.x);                // cubic Horner (num)
        ull pvb = f2fma(c2.y, tb, c3.x);
        pva = f2fma(pva, ta, c3.y); pvb = f2fma(pvb, tb, c3.y);
        pva = f2fma(pva, ta, c4.x); pvb = f2fma(pvb, tb, c4.x);
        ull pwa = f2fma(c4.y, ta, c5.x);                // cubic Horner (den)
        ull pwb = f2fma(c4.y, tb, c5.x);
        pwa = f2fma(pwa, ta, c5.y); pwb = f2fma(pwb, tb, c5.y);
        pwa = f2fma(pwa, ta, c6.x); pwb = f2fma(pwb, tb, c6.x);
        float qal, qah, qbl, qbh;
        upk2(qa, qal, qah);
        upk2(qb, qbl, qbh);
        ull ra = pk2(frcp(qal), frcp(qah));             // 1 MUFU per 4 nodes per point
        ull rb = pk2(frcp(qbl), frcp(qbh));
        numa = f2fma(pva, ra, numa);
        dena = f2fma(pwa, ra, dena);
        numb = f2fma(pvb, rb, numb);
        denb = f2fma(pwb, rb, denb);
    }
    float n0, n1, n2, n3, d0, d1, d2, d3;
    upk2(numa, n0, n1); upk2(dena, d0, d1);
    upk2(numb, n2, n3); upk2(denb, d2, d3);
    float4 o;
    o.x = n0 * frcp(d0);
    o.y = n1 * frcp(d1);
    o.z = n2 * frcp(d2);
    o.w = n3 * frcp(d3);
    ((float4*)out)[quad] = o;
}

// ---------------- launch ----------------
extern "C" void kernel_launch(void* const* d_in, const int* in_sizes, int n_in,
                              void* d_out, int out_size) {
    const float* x    = (const float*)d_in[0];
    const float* vals = (const float*)d_in[1];
    const float* pr   = (const float*)d_in[2];
    const float* pim  = (const float*)d_in[3];
    float* out = (float*)d_out;

    k_nodes<<<8, 128>>>();
    k_wts  <<<128, 256>>>(pr, pim);       // 8 warps/block, 1 warp per node
    k_coef <<<8, 32>>>(vals);             // 1 thread per group, full warps
    k_eval <<<NEVALC / 4 / 128, 128>>>(x, out);
}